// round 12
// baseline (speedup 1.0000x reference)
#include <cuda_runtime.h>
#include <cuda_fp16.h>
#include <mma.h>
#include <cstdint>
#include <cstddef>

using namespace nvcuda;

#define E_ 8
#define T_ 1024
#define D_ 2048
#define H_ 5632

// fp16 x copy, fp16 W3 (gate side-channel), fp16 y. W1/W2 converted in-loop.
__device__ __align__(256) __half g_hx [(size_t)E_ * T_ * D_];
__device__ __align__(256) __half g_hw3[(size_t)E_ * H_ * D_];
__device__ __align__(256) __half g_hy [(size_t)E_ * T_ * H_];

// ---------------- helpers ----------------
union Pack4 { uint2 u; __half2 h[2]; };
__device__ __forceinline__ uint2 pack4(float4 v) {
    Pack4 p;
    p.h[0] = __floats2half2_rn(v.x, v.y);
    p.h[1] = __floats2half2_rn(v.z, v.w);
    return p.u;
}
__device__ __forceinline__ float silu_mul(float v1, float v2) {
    return v2 * v1 * (1.0f / (1.0f + __expf(-v1)));
}
__device__ __forceinline__ void cp_async16(void* s, const void* g) {
    uint32_t sa = (uint32_t)__cvta_generic_to_shared(s);
    asm volatile("cp.async.cg.shared.global [%0], [%1], 16;" :: "r"(sa), "l"(g));
}
__device__ __forceinline__ void cp_commit() { asm volatile("cp.async.commit_group;"); }
template <int N>
__device__ __forceinline__ void cp_wait() { asm volatile("cp.async.wait_group %0;" :: "n"(N)); }

// ---------------- fp32 -> fp16 conversion: x ONLY ----------------
constexpr size_t XC  = (size_t)E_ * T_ * D_ / 4;
constexpr size_t W3C = (size_t)E_ * H_ * D_ / 4;   // 23,068,672 chunks

__global__ void __launch_bounds__(256)
cvt_x(const float* __restrict__ x)
{
    size_t i = (size_t)blockIdx.x * blockDim.x + threadIdx.x;
    if (i < XC) ((uint2*)g_hx)[i] = pack4(((const float4*)x)[i]);
}

// ---------------- zero-out for split-K atomics ----------------
constexpr size_t OC = (size_t)E_ * T_ * D_ / 4;   // out float4 chunks
__global__ void __launch_bounds__(256)
zero_out(float* __restrict__ Out)
{
    size_t i = (size_t)blockIdx.x * blockDim.x + threadIdx.x;
    if (i < OC) ((float4*)Out)[i] = make_float4(0.f, 0.f, 0.f, 0.f);
}

// ---------------- tiling ----------------
constexpr int BM   = 128;
constexpr int BK1  = 32;    // gate K slab (small => 16 staging regs for fp32 B)
constexpr int BK2  = 64;    // down K slab
constexpr int BN1  = 64;    // gate: N per gate matrix
constexpr int BN2  = 128;   // down: N tile
constexpr int LDA1 = BK1 + 8;   // 40
constexpr int LDA2 = BK2 + 8;   // 72
constexpr int LDB1 = BN1 + 8;   // 72
constexpr int LDB2 = BN2 + 8;   // 136
constexpr int STG1 = 4;
constexpr int STG2 = 3;

constexpr int A1_SLAB = BM * LDA1;    // 5120 halfs
constexpr int B1_SLAB = BK1 * LDB1;   // 2304
constexpr int A2_SLAB = BM * LDA2;    // 9216
constexpr int B2_SLAB = BK2 * LDB2;   // 8704

constexpr size_t SMEM1 = (size_t)STG1 * (A1_SLAB + 2 * B1_SLAB) * sizeof(__half); // 77824
constexpr size_t SMEM2 = (size_t)STG2 * (A2_SLAB + B2_SLAB) * sizeof(__half);     // 107520

constexpr int NK1 = D_ / BK1;   // 64
constexpr int NK2 = H_ / BK2;   // 88 (44 per split)
// gate grid = 8*88*8 = 5632 CTAs; W3 chunks/CTA = 4096 = 256thr x 16 iters
constexpr int W3_PER_CTA = (int)(W3C / (8ull * 88 * 8));  // 4096

// =====================================================================
// Kernel 1: y = silu(x@W1) * (x@W2)
// 256 threads, 8 warps (2M x 4N). Warp tile 64x16 per gate. 2 CTAs/SM.
// A (fp16 x) via cp.async; B (fp32 W1/W2) in-loop LDG->pack->STS (BK=32,
// 16 staging regs). W3 fp32->fp16 side-channel (first 16 iters).
// Grid: (T/BM, H/BN1, E) = (8, 88, 8)
// =====================================================================
__global__ void __launch_bounds__(256, 2)
ffn_gate_h(const float* __restrict__ W1, const float* __restrict__ W2,
           const float* __restrict__ W3src)
{
    extern __shared__ __align__(128) __half smem[];
    __half* sA  = smem;                     // [STG1][A1_SLAB]
    __half* sB1 = sA  + STG1 * A1_SLAB;     // [STG1][B1_SLAB]
    __half* sB2 = sB1 + STG1 * B1_SLAB;     // [STG1][B1_SLAB]

    const int tid  = threadIdx.x;
    const int warp = tid >> 5;
    const int lane = tid & 31;
    const int wm   = warp >> 2;   // 0..1
    const int wn   = warp & 3;    // 0..3
    const int e  = blockIdx.z;
    const int m0 = blockIdx.x * BM;
    const int n0 = blockIdx.y * BN1;
    const __half* Ax  = g_hx + (size_t)e * T_ * D_;
    const float*  B1g = W1   + (size_t)e * D_ * H_;
    const float*  B2g = W2   + (size_t)e * D_ * H_;

    // W3 side-channel
    const size_t cta_lin = (size_t)blockIdx.x + 8ull * (blockIdx.y + 88ull * blockIdx.z);
    const size_t w3_base = cta_lin * W3_PER_CTA + tid;
    const float4* w3s = (const float4*)W3src;
    uint2*        w3d = (uint2*)g_hw3;

    wmma::fragment<wmma::accumulator, 16, 16, 16, float> c1[4], c2[4];
    #pragma unroll
    for (int i = 0; i < 4; i++) {
        wmma::fill_fragment(c1[i], 0.0f);
        wmma::fill_fragment(c2[i], 0.0f);
    }

    // A: 128 rows x 4 chunks(8 halfs) = 512 -> 2/thread cp.async
    auto load_a = [&](int s, int kt) {
        const int k0 = kt * BK1;
        #pragma unroll
        for (int i = 0; i < 2; i++) {
            int u = tid + i * 256;
            int row = u >> 2, ch = u & 3;
            cp_async16(sA + s * A1_SLAB + row * LDA1 + ch * 8,
                       Ax + (size_t)(m0 + row) * D_ + k0 + ch * 8);
        }
        cp_commit();
    };

    // B (fp32): 2 mats x 32 rows x 16 float4 = 1024 -> 4/thread (16 regs)
    float4 rb[4];
    auto ldg_b = [&](int kt) {
        const int k0 = kt * BK1;
        #pragma unroll
        for (int i = 0; i < 4; i++) {
            int u = tid + i * 256;
            int mat = u >> 9;
            int rem = u & 511;
            int r = rem >> 4, ch = rem & 15;
            const float* src = (mat ? B2g : B1g) + (size_t)(k0 + r) * H_ + n0 + ch * 4;
            rb[i] = *(const float4*)src;
        }
    };
    auto sts_b = [&](int s) {
        #pragma unroll
        for (int i = 0; i < 4; i++) {
            int u = tid + i * 256;
            int mat = u >> 9;
            int rem = u & 511;
            int r = rem >> 4, ch = rem & 15;
            __half* dst = (mat ? sB2 : sB1) + s * B1_SLAB + r * LDB1 + ch * 4;
            *(uint2*)dst = pack4(rb[i]);
        }
    };

    #pragma unroll
    for (int p = 0; p < 3; p++) {    // stages 0..2
        ldg_b(p);
        load_a(p, p);
        sts_b(p);
    }

    for (int kt = 0; kt < NK1; kt++) {
        const int s = kt & 3;
        if (kt + 2 < NK1) cp_wait<2>(); else cp_wait<0>();
        __syncthreads();

        // W3 side-channel LDG (first 16 iters; store at iteration bottom)
        float4 w3v;
        const size_t w3i = w3_base + (size_t)kt * 256;
        if (kt < 16) w3v = w3s[w3i];

        if (kt + 3 < NK1) {
            ldg_b(kt + 3);                 // fp32 B into regs (latency hidden)
            load_a((kt + 3) & 3, kt + 3);  // async A
        }

        const __half* aW  = sA  + s * A1_SLAB + (wm * 64) * LDA1;
        const __half* b1W = sB1 + s * B1_SLAB + wn * 16;
        const __half* b2W = sB2 + s * B1_SLAB + wn * 16;
        #pragma unroll
        for (int kk = 0; kk < BK1 / 16; kk++) {
            wmma::fragment<wmma::matrix_a, 16, 16, 16, __half, wmma::row_major> a[4];
            #pragma unroll
            for (int i = 0; i < 4; i++)
                wmma::load_matrix_sync(a[i], aW + i * 16 * LDA1 + kk * 16, LDA1);
            {
                wmma::fragment<wmma::matrix_b, 16, 16, 16, __half, wmma::row_major> b;
                wmma::load_matrix_sync(b, b1W + kk * 16 * LDB1, LDB1);
                #pragma unroll
                for (int i = 0; i < 4; i++)
                    wmma::mma_sync(c1[i], a[i], b, c1[i]);
            }
            {
                wmma::fragment<wmma::matrix_b, 16, 16, 16, __half, wmma::row_major> b;
                wmma::load_matrix_sync(b, b2W + kk * 16 * LDB1, LDB1);
                #pragma unroll
                for (int i = 0; i < 4; i++)
                    wmma::mma_sync(c2[i], a[i], b, c2[i]);
            }
        }

        if (kt + 3 < NK1) sts_b((kt + 3) & 3);  // stage freed at kt-1
        if (kt < 16) w3d[w3i] = pack4(w3v);
        // no bottom barrier
    }

    // Epilogue: silu(c1)*c2 -> fp16 y via per-warp 64x16 fp32 smem patch
    __syncthreads();
    float* pw = (float*)smem + warp * (64 * 16);
    #pragma unroll
    for (int i = 0; i < 4; i++) {
        #pragma unroll
        for (int t = 0; t < c1[i].num_elements; t++)
            c1[i].x[t] = silu_mul(c1[i].x[t], c2[i].x[t]);
        wmma::store_matrix_sync(pw + i * 16 * 16, c1[i], 16, wmma::mem_row_major);
    }
    __syncwarp();
    __half* yb = g_hy + (size_t)e * T_ * H_ + (size_t)(m0 + wm * 64) * H_ + n0 + wn * 16;
    #pragma unroll
    for (int i = 0; i < 16; i++) {
        int u = lane + i * 32;
        int row = u >> 3, col2 = u & 7;
        float2 v = *(float2*)(pw + row * 16 + col2 * 2);
        *(__half2*)(yb + (size_t)row * H_ + col2 * 2) = __floats2half2_rn(v.x, v.y);
    }
}

// =====================================================================
// Kernel 2: out += y @ W3 (split-K x2, fp32 atomic epilogue)
// 256 threads, 8 warps (2M x 4N). Warp tile 64x32. 2 CTAs/SM.
// Grid: (T/BM, D/BN2, E*2) = (8, 16, 16) = 2048 CTAs = 6.9 waves
// =====================================================================
__global__ void __launch_bounds__(256, 2)
ffn_down_h(float* __restrict__ Out)
{
    extern __shared__ __align__(128) __half smem[];
    __half* sA = smem;                  // [STG2][A2_SLAB]
    __half* sB = sA + STG2 * A2_SLAB;   // [STG2][B2_SLAB]

    const int tid  = threadIdx.x;
    const int warp = tid >> 5;
    const int lane = tid & 31;
    const int wm   = warp >> 2;   // 0..1
    const int wn   = warp & 3;    // 0..3
    const int e  = blockIdx.z >> 1;
    const int sp = blockIdx.z & 1;        // K split half
    const int m0 = blockIdx.x * BM;
    const int n0 = blockIdx.y * BN2;
    const int kbase = sp * (NK2 / 2);     // 0 or 44 slabs
    const __half* Ay = g_hy  + (size_t)e * T_ * H_;
    const __half* Bg = g_hw3 + (size_t)e * H_ * D_;

    wmma::fragment<wmma::accumulator, 16, 16, 16, float> c[4][2];
    #pragma unroll
    for (int i = 0; i < 4; i++)
        #pragma unroll
        for (int j = 0; j < 2; j++)
            wmma::fill_fragment(c[i][j], 0.0f);

    auto load = [&](int s, int kt) {
        const int k0 = (kbase + kt) * BK2;
        #pragma unroll
        for (int i = 0; i < 4; i++) {
            int u = tid + i * 256;
            int row = u >> 3, ch = u & 7;
            cp_async16(sA + s * A2_SLAB + row * LDA2 + ch * 8,
                       Ay + (size_t)(m0 + row) * H_ + k0 + ch * 8);
        }
        #pragma unroll
        for (int i = 0; i < 4; i++) {
            int u = tid + i * 256;
            int r = u >> 4, ch = u & 15;
            cp_async16(sB + s * B2_SLAB + r * LDB2 + ch * 8,
                       Bg + (size_t)(k0 + r) * D_ + n0 + ch * 8);
        }
        cp_commit();
    };

    constexpr int NK = NK2 / 2;   // 44
    load(0, 0);
    load(1, 1);

    for (int kt = 0; kt < NK; kt++) {
        const int s = kt % 3;
        if (kt + 1 < NK) cp_wait<1>(); else cp_wait<0>();
        __syncthreads();
        if (kt + 2 < NK) load((kt + 2) % 3, kt + 2);

        const __half* aW = sA + s * A2_SLAB + (wm * 64) * LDA2;
        const __half* bW = sB + s * B2_SLAB + wn * 32;
        #pragma unroll
        for (int kk = 0; kk < BK2 / 16; kk++) {
            wmma::fragment<wmma::matrix_a, 16, 16, 16, __half, wmma::row_major> a[4];
            #pragma unroll
            for (int i = 0; i < 4; i++)
                wmma::load_matrix_sync(a[i], aW + i * 16 * LDA2 + kk * 16, LDA2);
            wmma::fragment<wmma::matrix_b, 16, 16, 16, __half, wmma::row_major> b[2];
            #pragma unroll
            for (int j = 0; j < 2; j++)
                wmma::load_matrix_sync(b[j], bW + kk * 16 * LDB2 + j * 16, LDB2);
            #pragma unroll
            for (int i = 0; i < 4; i++)
                #pragma unroll
                for (int j = 0; j < 2; j++)
                    wmma::mma_sync(c[i][j], a[i], b[j], c[i][j]);
        }
        // no bottom barrier
    }

    // Epilogue: per-warp 64x32 fp32 patch -> atomicAdd into Out
    __syncthreads();
    float* pw = (float*)smem + warp * (64 * 32);
    #pragma unroll
    for (int i = 0; i < 4; i++)
        #pragma unroll
        for (int j = 0; j < 2; j++)
            wmma::store_matrix_sync(pw + i * 16 * 32 + j * 16, c[i][j], 32,
                                    wmma::mem_row_major);
    __syncwarp();
    float* ob = Out + (size_t)e * T_ * D_ + (size_t)(m0 + wm * 64) * D_ + n0 + wn * 32;
    #pragma unroll
    for (int r = 0; r < 64; r++)
        atomicAdd(ob + (size_t)r * D_ + lane, pw[r * 32 + lane]);
}

// =====================================================================
extern "C" void kernel_launch(void* const* d_in, const int* in_sizes, int n_in,
                              void* d_out, int out_size)
{
    const float* x  = (const float*)d_in[0];
    const float* w1 = (const float*)d_in[1];
    const float* w2 = (const float*)d_in[2];
    const float* w3 = (const float*)d_in[3];
    float* out = (float*)d_out;
    (void)in_sizes; (void)n_in; (void)out_size;

    cudaFuncSetAttribute(ffn_gate_h, cudaFuncAttributeMaxDynamicSharedMemorySize, (int)SMEM1);
    cudaFuncSetAttribute(ffn_down_h, cudaFuncAttributeMaxDynamicSharedMemorySize, (int)SMEM2);

    cvt_x<<<(int)((XC + 255) / 256), 256>>>(x);
    zero_out<<<(int)((OC + 255) / 256), 256>>>(out);   // split-K accumulates

    dim3 g1(T_ / BM, H_ / BN1, E_);        // (8, 88, 8) = 5632 CTAs
    ffn_gate_h<<<g1, 256, SMEM1>>>(w1, w2, w3);

    dim3 g2(T_ / BM, D_ / BN2, E_ * 2);    // (8, 16, 16) = 2048 CTAs
    ffn_down_h<<<g2, 256, SMEM2>>>(out);
}

// round 13
// speedup vs baseline: 1.0394x; 1.0394x over previous
#include <cuda_runtime.h>
#include <cuda_fp16.h>
#include <mma.h>
#include <cstdint>
#include <cstddef>

using namespace nvcuda;

#define E_ 8
#define T_ 1024
#define D_ 2048
#define H_ 5632

// fp16 operand copies + y scratch. W3 converted by gate side-channel.
__device__ __align__(256) __half g_hx [(size_t)E_ * T_ * D_];
__device__ __align__(256) __half g_hw1[(size_t)E_ * D_ * H_];
__device__ __align__(256) __half g_hw2[(size_t)E_ * D_ * H_];
__device__ __align__(256) __half g_hw3[(size_t)E_ * H_ * D_];
__device__ __align__(256) __half g_hy [(size_t)E_ * T_ * H_];

// ---------------- helpers ----------------
union Pack4 { uint2 u; __half2 h[2]; };
__device__ __forceinline__ uint2 pack4(float4 v) {
    Pack4 p;
    p.h[0] = __floats2half2_rn(v.x, v.y);
    p.h[1] = __floats2half2_rn(v.z, v.w);
    return p.u;
}
__device__ __forceinline__ float silu_mul(float v1, float v2) {
    return v2 * v1 * (1.0f / (1.0f + __expf(-v1)));
}
__device__ __forceinline__ void cp_async16(void* s, const void* g) {
    uint32_t sa = (uint32_t)__cvta_generic_to_shared(s);
    asm volatile("cp.async.cg.shared.global [%0], [%1], 16;" :: "r"(sa), "l"(g));
}
__device__ __forceinline__ void cp_commit() { asm volatile("cp.async.commit_group;"); }
template <int N>
__device__ __forceinline__ void cp_wait() { asm volatile("cp.async.wait_group %0;" :: "n"(N)); }

// ---------- cvt3z: x/W1/W2 fp32->fp16 + zero out (one launch) ----------
constexpr size_t XC  = (size_t)E_ * T_ * D_ / 4;
constexpr size_t WC  = (size_t)E_ * D_ * H_ / 4;
constexpr size_t W3C = (size_t)E_ * H_ * D_ / 4;
constexpr size_t OC  = (size_t)E_ * T_ * D_ / 4;      // out float4 chunks
constexpr size_t TOT4 = XC + 2 * WC + OC;

__global__ void __launch_bounds__(256)
cvt3z_kernel(const float* __restrict__ x, const float* __restrict__ w1,
             const float* __restrict__ w2, float* __restrict__ out)
{
    size_t i = (size_t)blockIdx.x * blockDim.x + threadIdx.x;
    if (i >= TOT4) return;
    if (i >= XC + 2 * WC) {                     // zero the split-K output
        ((float4*)out)[i - XC - 2 * WC] = make_float4(0.f, 0.f, 0.f, 0.f);
        return;
    }
    const float4* src; uint2* dst; size_t off;
    if (i < XC)           { src = (const float4*)x;  dst = (uint2*)g_hx;  off = i; }
    else if (i < XC + WC) { src = (const float4*)w1; dst = (uint2*)g_hw1; off = i - XC; }
    else                  { src = (const float4*)w2; dst = (uint2*)g_hw2; off = i - XC - WC; }
    dst[off] = pack4(src[off]);
}

// ---------------- tiling: 2 CTAs/SM, 3-stage pipeline (R11 config) ----------------
constexpr int BM  = 128;
constexpr int BK  = 64;
constexpr int BN1 = 64;
constexpr int BN2 = 128;
constexpr int LDA  = BK  + 8;   // 72
constexpr int LDB1 = BN1 + 8;   // 72
constexpr int LDB2 = BN2 + 8;   // 136
constexpr int STG = 3;

constexpr int A_SLAB  = BM * LDA;    // 9216 halfs
constexpr int B1_SLAB = BK * LDB1;   // 4608
constexpr int B2_SLAB = BK * LDB2;   // 8704

constexpr size_t SMEM1 = (size_t)STG * (A_SLAB + 2 * B1_SLAB) * sizeof(__half); // 110592
constexpr size_t SMEM2 = (size_t)STG * (A_SLAB + B2_SLAB) * sizeof(__half);     // 107520

constexpr int NK1 = D_ / BK;          // 32
constexpr int NK2 = H_ / BK;          // 88 (44 per split)
constexpr int W3_PER_CTA = (int)(W3C / (8ull * 88 * 8));  // 4096 = 256thr x 16 iters

// =====================================================================
// Kernel 1: y = silu(x@W1) * (x@W2)  + W3 fp32->fp16 side-channel
// 256 threads, 8 warps (2M x 4N). Warp tile 64x16 per gate. 2 CTAs/SM.
// Grid: (T/BM, H/BN1, E) = (8, 88, 8)      [R11 configuration]
// =====================================================================
__global__ void __launch_bounds__(256, 2)
ffn_gate_h(const float* __restrict__ W3src)
{
    extern __shared__ __align__(128) __half smem[];
    __half* sA  = smem;                    // [STG][A_SLAB]
    __half* sB1 = sA  + STG * A_SLAB;      // [STG][B1_SLAB]
    __half* sB2 = sB1 + STG * B1_SLAB;     // [STG][B1_SLAB]

    const int tid  = threadIdx.x;
    const int warp = tid >> 5;
    const int lane = tid & 31;
    const int wm   = warp >> 2;   // 0..1
    const int wn   = warp & 3;    // 0..3
    const int e  = blockIdx.z;
    const int m0 = blockIdx.x * BM;
    const int n0 = blockIdx.y * BN1;
    const __half* Ax  = g_hx  + (size_t)e * T_ * D_;
    const __half* B1g = g_hw1 + (size_t)e * D_ * H_;
    const __half* B2g = g_hw2 + (size_t)e * D_ * H_;

    const size_t cta_lin = (size_t)blockIdx.x + 8ull * (blockIdx.y + 88ull * blockIdx.z);
    const size_t w3_base = cta_lin * W3_PER_CTA + tid;
    const float4* w3s = (const float4*)W3src;
    uint2*        w3d = (uint2*)g_hw3;

    wmma::fragment<wmma::accumulator, 16, 16, 16, float> c1[4], c2[4];
    #pragma unroll
    for (int i = 0; i < 4; i++) {
        wmma::fill_fragment(c1[i], 0.0f);
        wmma::fill_fragment(c2[i], 0.0f);
    }

    auto load = [&](int s, int kt) {
        const int k0 = kt * BK;
        #pragma unroll
        for (int i = 0; i < 4; i++) {
            int u = tid + i * 256;
            int row = u >> 3, ch = u & 7;
            cp_async16(sA + s * A_SLAB + row * LDA + ch * 8,
                       Ax + (size_t)(m0 + row) * D_ + k0 + ch * 8);
        }
        #pragma unroll
        for (int i = 0; i < 4; i++) {
            int u = tid + i * 256;
            int mat = u >> 9;
            int rem = u & 511;
            int r = rem >> 3, ch = rem & 7;
            const __half* src = (mat ? B2g : B1g) + (size_t)(k0 + r) * H_ + n0 + ch * 8;
            __half* dst = (mat ? sB2 : sB1) + s * B1_SLAB + r * LDB1 + ch * 8;
            cp_async16(dst, src);
        }
        cp_commit();
    };

    load(0, 0);
    load(1, 1);

    for (int kt = 0; kt < NK1; kt++) {
        const int s = kt % 3;
        if (kt + 1 < NK1) cp_wait<1>(); else cp_wait<0>();
        __syncthreads();

        float4 w3v;
        const size_t w3i = w3_base + (size_t)kt * 256;
        if (kt < 16) w3v = w3s[w3i];

        if (kt + 2 < NK1) load((kt + 2) % 3, kt + 2);

        const __half* aW  = sA  + s * A_SLAB  + (wm * 64) * LDA;
        const __half* b1W = sB1 + s * B1_SLAB + wn * 16;
        const __half* b2W = sB2 + s * B1_SLAB + wn * 16;
        #pragma unroll
        for (int kk = 0; kk < BK / 16; kk++) {
            wmma::fragment<wmma::matrix_a, 16, 16, 16, __half, wmma::row_major> a[4];
            #pragma unroll
            for (int i = 0; i < 4; i++)
                wmma::load_matrix_sync(a[i], aW + i * 16 * LDA + kk * 16, LDA);
            {
                wmma::fragment<wmma::matrix_b, 16, 16, 16, __half, wmma::row_major> b;
                wmma::load_matrix_sync(b, b1W + kk * 16 * LDB1, LDB1);
                #pragma unroll
                for (int i = 0; i < 4; i++)
                    wmma::mma_sync(c1[i], a[i], b, c1[i]);
            }
            {
                wmma::fragment<wmma::matrix_b, 16, 16, 16, __half, wmma::row_major> b;
                wmma::load_matrix_sync(b, b2W + kk * 16 * LDB1, LDB1);
                #pragma unroll
                for (int i = 0; i < 4; i++)
                    wmma::mma_sync(c2[i], a[i], b, c2[i]);
            }
        }

        if (kt < 16) w3d[w3i] = pack4(w3v);
        // no bottom barrier
    }

    // Epilogue
    __syncthreads();
    float* pw = (float*)smem + warp * (64 * 16);
    #pragma unroll
    for (int i = 0; i < 4; i++) {
        #pragma unroll
        for (int t = 0; t < c1[i].num_elements; t++)
            c1[i].x[t] = silu_mul(c1[i].x[t], c2[i].x[t]);
        wmma::store_matrix_sync(pw + i * 16 * 16, c1[i], 16, wmma::mem_row_major);
    }
    __syncwarp();
    __half* yb = g_hy + (size_t)e * T_ * H_ + (size_t)(m0 + wm * 64) * H_ + n0 + wn * 16;
    #pragma unroll
    for (int i = 0; i < 16; i++) {
        int u = lane + i * 32;
        int row = u >> 3, col2 = u & 7;
        float2 v = *(float2*)(pw + row * 16 + col2 * 2);
        *(__half2*)(yb + (size_t)row * H_ + col2 * 2) = __floats2half2_rn(v.x, v.y);
    }
}

// =====================================================================
// Kernel 2: out += y @ W3   (split-K x2, fp32 atomic epilogue)
// 256 threads, 8 warps (2M x 4N). Warp tile 64x32. 2 CTAs/SM.
// Grid: (T/BM, D/BN2, E*2) = (8, 16, 16) = 2048 CTAs = 6.9 waves
// =====================================================================
__global__ void __launch_bounds__(256, 2)
ffn_down_h(float* __restrict__ Out)
{
    extern __shared__ __align__(128) __half smem[];
    __half* sA = smem;                 // [STG][A_SLAB]
    __half* sB = sA + STG * A_SLAB;    // [STG][B2_SLAB]

    const int tid  = threadIdx.x;
    const int warp = tid >> 5;
    const int lane = tid & 31;
    const int wm   = warp >> 2;   // 0..1
    const int wn   = warp & 3;    // 0..3
    const int e  = blockIdx.z >> 1;
    const int sp = blockIdx.z & 1;
    const int m0 = blockIdx.x * BM;
    const int n0 = blockIdx.y * BN2;
    const int kbase = sp * (NK2 / 2);   // 0 or 44
    const __half* Ay = g_hy  + (size_t)e * T_ * H_;
    const __half* Bg = g_hw3 + (size_t)e * H_ * D_;

    wmma::fragment<wmma::accumulator, 16, 16, 16, float> c[4][2];
    #pragma unroll
    for (int i = 0; i < 4; i++)
        #pragma unroll
        for (int j = 0; j < 2; j++)
            wmma::fill_fragment(c[i][j], 0.0f);

    auto load = [&](int s, int kt) {
        const int k0 = (kbase + kt) * BK;
        #pragma unroll
        for (int i = 0; i < 4; i++) {
            int u = tid + i * 256;
            int row = u >> 3, ch = u & 7;
            cp_async16(sA + s * A_SLAB + row * LDA + ch * 8,
                       Ay + (size_t)(m0 + row) * H_ + k0 + ch * 8);
        }
        #pragma unroll
        for (int i = 0; i < 4; i++) {
            int u = tid + i * 256;
            int r = u >> 4, ch = u & 15;
            cp_async16(sB + s * B2_SLAB + r * LDB2 + ch * 8,
                       Bg + (size_t)(k0 + r) * D_ + n0 + ch * 8);
        }
        cp_commit();
    };

    constexpr int NK = NK2 / 2;   // 44
    load(0, 0);
    load(1, 1);

    for (int kt = 0; kt < NK; kt++) {
        const int s = kt % 3;
        if (kt + 1 < NK) cp_wait<1>(); else cp_wait<0>();
        __syncthreads();
        if (kt + 2 < NK) load((kt + 2) % 3, kt + 2);

        const __half* aW = sA + s * A_SLAB  + (wm * 64) * LDA;
        const __half* bW = sB + s * B2_SLAB + wn * 32;
        #pragma unroll
        for (int kk = 0; kk < BK / 16; kk++) {
            wmma::fragment<wmma::matrix_a, 16, 16, 16, __half, wmma::row_major> a[4];
            #pragma unroll
            for (int i = 0; i < 4; i++)
                wmma::load_matrix_sync(a[i], aW + i * 16 * LDA + kk * 16, LDA);
            wmma::fragment<wmma::matrix_b, 16, 16, 16, __half, wmma::row_major> b[2];
            #pragma unroll
            for (int j = 0; j < 2; j++)
                wmma::load_matrix_sync(b[j], bW + kk * 16 * LDB2 + j * 16, LDB2);
            #pragma unroll
            for (int i = 0; i < 4; i++)
                #pragma unroll
                for (int j = 0; j < 2; j++)
                    wmma::mma_sync(c[i][j], a[i], b[j], c[i][j]);
        }
        // no bottom barrier
    }

    // Epilogue: per-warp 64x32 fp32 patch -> atomicAdd into Out
    __syncthreads();
    float* pw = (float*)smem + warp * (64 * 32);
    #pragma unroll
    for (int i = 0; i < 4; i++)
        #pragma unroll
        for (int j = 0; j < 2; j++)
            wmma::store_matrix_sync(pw + i * 16 * 32 + j * 16, c[i][j], 32,
                                    wmma::mem_row_major);
    __syncwarp();
    float* ob = Out + (size_t)e * T_ * D_ + (size_t)(m0 + wm * 64) * D_ + n0 + wn * 32;
    #pragma unroll
    for (int r = 0; r < 64; r++)
        atomicAdd(ob + (size_t)r * D_ + lane, pw[r * 32 + lane]);
}

// =====================================================================
extern "C" void kernel_launch(void* const* d_in, const int* in_sizes, int n_in,
                              void* d_out, int out_size)
{
    const float* x  = (const float*)d_in[0];
    const float* w1 = (const float*)d_in[1];
    const float* w2 = (const float*)d_in[2];
    const float* w3 = (const float*)d_in[3];
    float* out = (float*)d_out;
    (void)in_sizes; (void)n_in; (void)out_size;

    cudaFuncSetAttribute(ffn_gate_h, cudaFuncAttributeMaxDynamicSharedMemorySize, (int)SMEM1);
    cudaFuncSetAttribute(ffn_down_h, cudaFuncAttributeMaxDynamicSharedMemorySize, (int)SMEM2);

    cvt3z_kernel<<<(int)((TOT4 + 255) / 256), 256>>>(x, w1, w2, out);

    dim3 g1(T_ / BM, H_ / BN1, E_);        // (8, 88, 8)
    ffn_gate_h<<<g1, 256, SMEM1>>>(w3);

    dim3 g2(T_ / BM, D_ / BN2, E_ * 2);    // (8, 16, 16)
    ffn_down_h<<<g2, 256, SMEM2>>>(out);
}

// round 14
// speedup vs baseline: 1.0742x; 1.0335x over previous
#include <cuda_runtime.h>
#include <cuda_fp16.h>
#include <mma.h>
#include <cstdint>
#include <cstddef>

using namespace nvcuda;

#define E_ 8
#define T_ 1024
#define D_ 2048
#define H_ 5632

// fp16 operand copies + y scratch. W3 converted by gate side-channel.
__device__ __align__(256) __half g_hx [(size_t)E_ * T_ * D_];
__device__ __align__(256) __half g_hw1[(size_t)E_ * D_ * H_];
__device__ __align__(256) __half g_hw2[(size_t)E_ * D_ * H_];
__device__ __align__(256) __half g_hw3[(size_t)E_ * H_ * D_];
__device__ __align__(256) __half g_hy [(size_t)E_ * T_ * H_];

// ---------------- helpers ----------------
union Pack4 { uint2 u; __half2 h[2]; };
__device__ __forceinline__ uint2 pack4(float4 v) {
    Pack4 p;
    p.h[0] = __floats2half2_rn(v.x, v.y);
    p.h[1] = __floats2half2_rn(v.z, v.w);
    return p.u;
}
__device__ __forceinline__ float silu_mul(float v1, float v2) {
    return v2 * v1 * (1.0f / (1.0f + __expf(-v1)));
}
__device__ __forceinline__ void cp_async16(void* s, const void* g) {
    uint32_t sa = (uint32_t)__cvta_generic_to_shared(s);
    asm volatile("cp.async.cg.shared.global [%0], [%1], 16;" :: "r"(sa), "l"(g));
}
__device__ __forceinline__ void cp_commit() { asm volatile("cp.async.commit_group;"); }
template <int N>
__device__ __forceinline__ void cp_wait() { asm volatile("cp.async.wait_group %0;" :: "n"(N)); }

// ---------- cvt3: x/W1/W2 fp32->fp16, 32B per thread (paired float4) ----------
constexpr size_t XC  = (size_t)E_ * T_ * D_ / 4;   // float4 chunks (even)
constexpr size_t WC  = (size_t)E_ * D_ * H_ / 4;   // (even)
constexpr size_t W3C = (size_t)E_ * H_ * D_ / 4;
constexpr size_t TOT3 = XC + 2 * WC;
constexpr size_t TOT3P = TOT3 / 2;                 // pairs

__global__ void __launch_bounds__(256)
cvt3_kernel(const float* __restrict__ x, const float* __restrict__ w1,
            const float* __restrict__ w2)
{
    size_t j = (size_t)blockIdx.x * blockDim.x + threadIdx.x;
    if (j >= TOT3P) return;
    size_t i = 2 * j;   // region boundaries are even -> pair stays in one region
    const float4* src; uint2* dst; size_t off;
    if (i < XC)           { src = (const float4*)x;  dst = (uint2*)g_hx;  off = i; }
    else if (i < XC + WC) { src = (const float4*)w1; dst = (uint2*)g_hw1; off = i - XC; }
    else                  { src = (const float4*)w2; dst = (uint2*)g_hw2; off = i - XC - WC; }
    float4 a = src[off], b = src[off + 1];
    uint2 pa = pack4(a), pb = pack4(b);
    uint4 o = make_uint4(pa.x, pa.y, pb.x, pb.y);
    *(uint4*)(dst + off) = o;                      // 16B-aligned (off even)
}

// ---------------- tiling: 2 CTAs/SM, 3-stage pipeline (R11 config) ----------------
constexpr int BM  = 128;
constexpr int BK  = 64;
constexpr int BN1 = 64;
constexpr int BN2 = 128;
constexpr int LDA  = BK  + 8;   // 72
constexpr int LDB1 = BN1 + 8;   // 72
constexpr int LDB2 = BN2 + 8;   // 136
constexpr int STG = 3;

constexpr int A_SLAB  = BM * LDA;    // 9216 halfs
constexpr int B1_SLAB = BK * LDB1;   // 4608
constexpr int B2_SLAB = BK * LDB2;   // 8704

constexpr size_t SMEM1 = (size_t)STG * (A_SLAB + 2 * B1_SLAB) * sizeof(__half); // 110592
constexpr size_t SMEM2 = (size_t)STG * (A_SLAB + B2_SLAB) * sizeof(__half);     // 107520

constexpr int NK1 = D_ / BK;          // 32
constexpr int NK2 = H_ / BK;          // 88
constexpr int W3_PER_CTA = (int)(W3C / (8ull * 88 * 8));  // 4096 = 256thr x 16 iters

// =====================================================================
// Kernel 1: y = silu(x@W1) * (x@W2)  + W3 fp32->fp16 side-channel
// 256 threads, 8 warps (2M x 4N). Warp tile 64x16 per gate. 2 CTAs/SM.
// Grid: (T/BM, H/BN1, E) = (8, 88, 8)      [R11 configuration]
// =====================================================================
__global__ void __launch_bounds__(256, 2)
ffn_gate_h(const float* __restrict__ W3src)
{
    extern __shared__ __align__(128) __half smem[];
    __half* sA  = smem;                    // [STG][A_SLAB]
    __half* sB1 = sA  + STG * A_SLAB;      // [STG][B1_SLAB]
    __half* sB2 = sB1 + STG * B1_SLAB;     // [STG][B1_SLAB]

    const int tid  = threadIdx.x;
    const int warp = tid >> 5;
    const int lane = tid & 31;
    const int wm   = warp >> 2;   // 0..1
    const int wn   = warp & 3;    // 0..3
    const int e  = blockIdx.z;
    const int m0 = blockIdx.x * BM;
    const int n0 = blockIdx.y * BN1;
    const __half* Ax  = g_hx  + (size_t)e * T_ * D_;
    const __half* B1g = g_hw1 + (size_t)e * D_ * H_;
    const __half* B2g = g_hw2 + (size_t)e * D_ * H_;

    const size_t cta_lin = (size_t)blockIdx.x + 8ull * (blockIdx.y + 88ull * blockIdx.z);
    const size_t w3_base = cta_lin * W3_PER_CTA + tid;
    const float4* w3s = (const float4*)W3src;
    uint2*        w3d = (uint2*)g_hw3;

    wmma::fragment<wmma::accumulator, 16, 16, 16, float> c1[4], c2[4];
    #pragma unroll
    for (int i = 0; i < 4; i++) {
        wmma::fill_fragment(c1[i], 0.0f);
        wmma::fill_fragment(c2[i], 0.0f);
    }

    auto load = [&](int s, int kt) {
        const int k0 = kt * BK;
        #pragma unroll
        for (int i = 0; i < 4; i++) {
            int u = tid + i * 256;
            int row = u >> 3, ch = u & 7;
            cp_async16(sA + s * A_SLAB + row * LDA + ch * 8,
                       Ax + (size_t)(m0 + row) * D_ + k0 + ch * 8);
        }
        #pragma unroll
        for (int i = 0; i < 4; i++) {
            int u = tid + i * 256;
            int mat = u >> 9;
            int rem = u & 511;
            int r = rem >> 3, ch = rem & 7;
            const __half* src = (mat ? B2g : B1g) + (size_t)(k0 + r) * H_ + n0 + ch * 8;
            __half* dst = (mat ? sB2 : sB1) + s * B1_SLAB + r * LDB1 + ch * 8;
            cp_async16(dst, src);
        }
        cp_commit();
    };

    load(0, 0);
    load(1, 1);

    for (int kt = 0; kt < NK1; kt++) {
        const int s = kt % 3;
        if (kt + 1 < NK1) cp_wait<1>(); else cp_wait<0>();
        __syncthreads();

        float4 w3v;
        const size_t w3i = w3_base + (size_t)kt * 256;
        if (kt < 16) w3v = w3s[w3i];

        if (kt + 2 < NK1) load((kt + 2) % 3, kt + 2);

        const __half* aW  = sA  + s * A_SLAB  + (wm * 64) * LDA;
        const __half* b1W = sB1 + s * B1_SLAB + wn * 16;
        const __half* b2W = sB2 + s * B1_SLAB + wn * 16;
        #pragma unroll
        for (int kk = 0; kk < BK / 16; kk++) {
            wmma::fragment<wmma::matrix_a, 16, 16, 16, __half, wmma::row_major> a[4];
            #pragma unroll
            for (int i = 0; i < 4; i++)
                wmma::load_matrix_sync(a[i], aW + i * 16 * LDA + kk * 16, LDA);
            {
                wmma::fragment<wmma::matrix_b, 16, 16, 16, __half, wmma::row_major> b;
                wmma::load_matrix_sync(b, b1W + kk * 16 * LDB1, LDB1);
                #pragma unroll
                for (int i = 0; i < 4; i++)
                    wmma::mma_sync(c1[i], a[i], b, c1[i]);
            }
            {
                wmma::fragment<wmma::matrix_b, 16, 16, 16, __half, wmma::row_major> b;
                wmma::load_matrix_sync(b, b2W + kk * 16 * LDB1, LDB1);
                #pragma unroll
                for (int i = 0; i < 4; i++)
                    wmma::mma_sync(c2[i], a[i], b, c2[i]);
            }
        }

        if (kt < 16) w3d[w3i] = pack4(w3v);
        // no bottom barrier: next iteration's top sync orders stage reuse
    }

    // Epilogue: silu(c1)*c2 -> fp16 y via per-warp 64x16 fp32 smem patch
    __syncthreads();
    float* pw = (float*)smem + warp * (64 * 16);
    #pragma unroll
    for (int i = 0; i < 4; i++) {
        #pragma unroll
        for (int t = 0; t < c1[i].num_elements; t++)
            c1[i].x[t] = silu_mul(c1[i].x[t], c2[i].x[t]);
        wmma::store_matrix_sync(pw + i * 16 * 16, c1[i], 16, wmma::mem_row_major);
    }
    __syncwarp();
    __half* yb = g_hy + (size_t)e * T_ * H_ + (size_t)(m0 + wm * 64) * H_ + n0 + wn * 16;
    #pragma unroll
    for (int i = 0; i < 16; i++) {
        int u = lane + i * 32;
        int row = u >> 3, col2 = u & 7;
        float2 v = *(float2*)(pw + row * 16 + col2 * 2);
        *(__half2*)(yb + (size_t)row * H_ + col2 * 2) = __floats2half2_rn(v.x, v.y);
    }
}

// =====================================================================
// Kernel 2: out = y @ W3   (all fp16 operands)
// 256 threads, 8 warps (2M x 4N). Warp tile 64x32. 2 CTAs/SM.
// Grid: (T/BM, D/BN2, E) = (8, 16, 8) = 1024 CTAs     [R11 configuration]
// =====================================================================
__global__ void __launch_bounds__(256, 2)
ffn_down_h(float* __restrict__ Out)
{
    extern __shared__ __align__(128) __half smem[];
    __half* sA = smem;                 // [STG][A_SLAB]
    __half* sB = sA + STG * A_SLAB;    // [STG][B2_SLAB]

    const int tid  = threadIdx.x;
    const int warp = tid >> 5;
    const int wm   = warp >> 2;   // 0..1
    const int wn   = warp & 3;    // 0..3
    const int e  = blockIdx.z;
    const int m0 = blockIdx.x * BM;
    const int n0 = blockIdx.y * BN2;
    const __half* Ay = g_hy  + (size_t)e * T_ * H_;
    const __half* Bg = g_hw3 + (size_t)e * H_ * D_;

    wmma::fragment<wmma::accumulator, 16, 16, 16, float> c[4][2];
    #pragma unroll
    for (int i = 0; i < 4; i++)
        #pragma unroll
        for (int j = 0; j < 2; j++)
            wmma::fill_fragment(c[i][j], 0.0f);

    auto load = [&](int s, int kt) {
        const int k0 = kt * BK;
        #pragma unroll
        for (int i = 0; i < 4; i++) {
            int u = tid + i * 256;
            int row = u >> 3, ch = u & 7;
            cp_async16(sA + s * A_SLAB + row * LDA + ch * 8,
                       Ay + (size_t)(m0 + row) * H_ + k0 + ch * 8);
        }
        #pragma unroll
        for (int i = 0; i < 4; i++) {
            int u = tid + i * 256;
            int r = u >> 4, ch = u & 15;
            cp_async16(sB + s * B2_SLAB + r * LDB2 + ch * 8,
                       Bg + (size_t)(k0 + r) * D_ + n0 + ch * 8);
        }
        cp_commit();
    };

    load(0, 0);
    load(1, 1);

    for (int kt = 0; kt < NK2; kt++) {
        const int s = kt % 3;
        if (kt + 1 < NK2) cp_wait<1>(); else cp_wait<0>();
        __syncthreads();
        if (kt + 2 < NK2) load((kt + 2) % 3, kt + 2);

        const __half* aW = sA + s * A_SLAB  + (wm * 64) * LDA;
        const __half* bW = sB + s * B2_SLAB + wn * 32;
        #pragma unroll
        for (int kk = 0; kk < BK / 16; kk++) {
            wmma::fragment<wmma::matrix_a, 16, 16, 16, __half, wmma::row_major> a[4];
            #pragma unroll
            for (int i = 0; i < 4; i++)
                wmma::load_matrix_sync(a[i], aW + i * 16 * LDA + kk * 16, LDA);
            wmma::fragment<wmma::matrix_b, 16, 16, 16, __half, wmma::row_major> b[2];
            #pragma unroll
            for (int j = 0; j < 2; j++)
                wmma::load_matrix_sync(b[j], bW + kk * 16 * LDB2 + j * 16, LDB2);
            #pragma unroll
            for (int i = 0; i < 4; i++)
                #pragma unroll
                for (int j = 0; j < 2; j++)
                    wmma::mma_sync(c[i][j], a[i], b[j], c[i][j]);
        }
        // no bottom barrier
    }

    #pragma unroll
    for (int i = 0; i < 4; i++)
        #pragma unroll
        for (int j = 0; j < 2; j++)
            wmma::store_matrix_sync(
                Out + (size_t)e * T_ * D_
                    + (size_t)(m0 + wm * 64 + i * 16) * D_ + (n0 + wn * 32 + j * 16),
                c[i][j], D_, wmma::mem_row_major);
}

// =====================================================================
extern "C" void kernel_launch(void* const* d_in, const int* in_sizes, int n_in,
                              void* d_out, int out_size)
{
    const float* x  = (const float*)d_in[0];
    const float* w1 = (const float*)d_in[1];
    const float* w2 = (const float*)d_in[2];
    const float* w3 = (const float*)d_in[3];
    float* out = (float*)d_out;
    (void)in_sizes; (void)n_in; (void)out_size;

    cudaFuncSetAttribute(ffn_gate_h, cudaFuncAttributeMaxDynamicSharedMemorySize, (int)SMEM1);
    cudaFuncSetAttribute(ffn_down_h, cudaFuncAttributeMaxDynamicSharedMemorySize, (int)SMEM2);

    cvt3_kernel<<<(int)((TOT3P + 255) / 256), 256>>>(x, w1, w2);

    dim3 g1(T_ / BM, H_ / BN1, E_);        // (8, 88, 8)
    ffn_gate_h<<<g1, 256, SMEM1>>>(w3);

    dim3 g2(T_ / BM, D_ / BN2, E_);        // (8, 16, 8)
    ffn_down_h<<<g2, 256, SMEM2>>>(out);
}